// round 1
// baseline (speedup 1.0000x reference)
#include <cuda_runtime.h>
#include <cuda_bf16.h>

// Problem constants (fixed by the reference):
//   M = 64 (mlp_dim), G = 48 (gaussians), N = 4096 (points), GRID_RANGE = 2.0
// Inputs (metadata order):
//   0: x (N), 1: y (N), 2: z (N), 3: mu_x (M*G), 4: mu_y (M*G), 5: mu_z (M*G),
//   6: sigmas (M*G*3), 7: r (M*G*4), 8: weight (M*G)
// Output: float (N, M) row-major -> out[n*M + m]

#define MDIM 64
#define GDIM 48

// Per-(m,g) polynomial coefficients, 12 floats each:
// [a00, a11, a22, 2*a01, 2*a02, 2*a12, b0, b1, b2, c, w, pad]
// where A = k*C, k = -0.5*log2(e), C = R diag(1/s^2) R^T,
// b = -2*A*mu, c = mu^T A mu.  Then exponent-of-2 argument is
// q = A-quadform(X) + b.X + c  and pdf = exp2(q).
__device__ float g_coef[MDIM * GDIM * 12];

__global__ void precompute_kernel(const float* __restrict__ mu_x,
                                  const float* __restrict__ mu_y,
                                  const float* __restrict__ mu_z,
                                  const float* __restrict__ sigmas,
                                  const float* __restrict__ r,
                                  const float* __restrict__ weight) {
    int idx = blockIdx.x * blockDim.x + threadIdx.x;
    if (idx >= MDIM * GDIM) return;

    // quaternion -> rotation
    float qw = r[idx * 4 + 0];
    float qx = r[idx * 4 + 1];
    float qy = r[idx * 4 + 2];
    float qz = r[idx * 4 + 3];
    float inv = rsqrtf(qw * qw + qx * qx + qy * qy + qz * qz);
    qw *= inv; qx *= inv; qy *= inv; qz *= inv;

    float R[3][3];
    R[0][0] = 1.f - 2.f * (qy * qy + qz * qz);
    R[0][1] = 2.f * (qx * qy - qw * qz);
    R[0][2] = 2.f * (qx * qz + qw * qy);
    R[1][0] = 2.f * (qx * qy + qw * qz);
    R[1][1] = 1.f - 2.f * (qx * qx + qz * qz);
    R[1][2] = 2.f * (qy * qz - qw * qx);
    R[2][0] = 2.f * (qx * qz - qw * qy);
    R[2][1] = 2.f * (qy * qz + qw * qx);
    R[2][2] = 1.f - 2.f * (qx * qx + qy * qy);

    float s0 = sigmas[idx * 3 + 0];
    float s1 = sigmas[idx * 3 + 1];
    float s2 = sigmas[idx * 3 + 2];
    float is0 = 1.f / (s0 * s0);
    float is1 = 1.f / (s1 * s1);
    float is2 = 1.f / (s2 * s2);

    // C = R diag(1/s^2) R^T  (symmetric)
    float C[3][3];
    #pragma unroll
    for (int i = 0; i < 3; ++i)
        #pragma unroll
        for (int j = 0; j < 3; ++j)
            C[i][j] = R[i][0] * R[j][0] * is0 +
                      R[i][1] * R[j][1] * is1 +
                      R[i][2] * R[j][2] * is2;

    const float k = -0.72134752044448169f;  // -0.5 * log2(e)
    float A[3][3];
    #pragma unroll
    for (int i = 0; i < 3; ++i)
        #pragma unroll
        for (int j = 0; j < 3; ++j)
            A[i][j] = k * C[i][j];

    float m0 = mu_x[idx], m1 = mu_y[idx], m2 = mu_z[idx];

    float b0 = -2.f * (A[0][0] * m0 + A[0][1] * m1 + A[0][2] * m2);
    float b1 = -2.f * (A[1][0] * m0 + A[1][1] * m1 + A[1][2] * m2);
    float b2 = -2.f * (A[2][0] * m0 + A[2][1] * m1 + A[2][2] * m2);
    float c  = A[0][0] * m0 * m0 + A[1][1] * m1 * m1 + A[2][2] * m2 * m2
             + 2.f * (A[0][1] * m0 * m1 + A[0][2] * m0 * m2 + A[1][2] * m1 * m2);

    float* dst = g_coef + idx * 12;
    dst[0]  = A[0][0];
    dst[1]  = A[1][1];
    dst[2]  = A[2][2];
    dst[3]  = 2.f * A[0][1];
    dst[4]  = 2.f * A[0][2];
    dst[5]  = 2.f * A[1][2];
    dst[6]  = b0;
    dst[7]  = b1;
    dst[8]  = b2;
    dst[9]  = c;
    dst[10] = weight[idx];
    dst[11] = 0.f;
}

__device__ __forceinline__ float fast_exp2(float q) {
    float p;
    asm("ex2.approx.ftz.f32 %0, %1;" : "=f"(p) : "f"(q));
    return p;
}

// One m per block; 128 threads x 2 points = 256 points per block.
__global__ __launch_bounds__(128) void gauss_kernel(const float* __restrict__ xs,
                                                    const float* __restrict__ ys,
                                                    const float* __restrict__ zs,
                                                    float* __restrict__ out,
                                                    int N) {
    __shared__ float4 sc[GDIM * 3];
    const int m = blockIdx.y;
    const float4* src = reinterpret_cast<const float4*>(g_coef + m * GDIM * 12);
    for (int i = threadIdx.x; i < GDIM * 3; i += blockDim.x) sc[i] = src[i];
    __syncthreads();

    const int n0 = blockIdx.x * 256 + threadIdx.x;
    const int n1 = n0 + 128;

    float x0 = 0.f, y0 = 0.f, z0 = 0.f;
    float x1 = 0.f, y1 = 0.f, z1 = 0.f;
    if (n0 < N) {
        x0 = xs[n0];
        y0 = ys[n0] + 1.f;   // (y+1)/2 * GRID_RANGE with GRID_RANGE=2 -> y+1
        z0 = zs[n0] + 1.f;
    }
    if (n1 < N) {
        x1 = xs[n1];
        y1 = ys[n1] + 1.f;
        z1 = zs[n1] + 1.f;
    }

    // point features, shared across all 48 gaussians
    const float xx0 = x0 * x0, yy0 = y0 * y0, zz0 = z0 * z0;
    const float xy0 = x0 * y0, xz0 = x0 * z0, yz0 = y0 * z0;
    const float xx1 = x1 * x1, yy1 = y1 * y1, zz1 = z1 * z1;
    const float xy1 = x1 * y1, xz1 = x1 * z1, yz1 = y1 * z1;

    float acc0 = 0.f, acc1 = 0.f;

    #pragma unroll
    for (int g = 0; g < GDIM; ++g) {
        const float4 cA = sc[g * 3 + 0];   // a00 a11 a22 2a01
        const float4 cB = sc[g * 3 + 1];   // 2a02 2a12 b0 b1
        const float4 cC = sc[g * 3 + 2];   // b2 c w pad

        float q0 = cC.y;
        q0 = fmaf(cA.x, xx0, q0);
        q0 = fmaf(cA.y, yy0, q0);
        q0 = fmaf(cA.z, zz0, q0);
        q0 = fmaf(cA.w, xy0, q0);
        q0 = fmaf(cB.x, xz0, q0);
        q0 = fmaf(cB.y, yz0, q0);
        q0 = fmaf(cB.z, x0, q0);
        q0 = fmaf(cB.w, y0, q0);
        q0 = fmaf(cC.x, z0, q0);

        float q1 = cC.y;
        q1 = fmaf(cA.x, xx1, q1);
        q1 = fmaf(cA.y, yy1, q1);
        q1 = fmaf(cA.z, zz1, q1);
        q1 = fmaf(cA.w, xy1, q1);
        q1 = fmaf(cB.x, xz1, q1);
        q1 = fmaf(cB.y, yz1, q1);
        q1 = fmaf(cB.z, x1, q1);
        q1 = fmaf(cB.w, y1, q1);
        q1 = fmaf(cC.x, z1, q1);

        acc0 = fmaf(cC.z, fast_exp2(q0), acc0);
        acc1 = fmaf(cC.z, fast_exp2(q1), acc1);
    }

    if (n0 < N) out[n0 * MDIM + m] = acc0;
    if (n1 < N) out[n1 * MDIM + m] = acc1;
}

extern "C" void kernel_launch(void* const* d_in, const int* in_sizes, int n_in,
                              void* d_out, int out_size) {
    const float* x      = (const float*)d_in[0];
    const float* y      = (const float*)d_in[1];
    const float* z      = (const float*)d_in[2];
    const float* mu_x   = (const float*)d_in[3];
    const float* mu_y   = (const float*)d_in[4];
    const float* mu_z   = (const float*)d_in[5];
    const float* sigmas = (const float*)d_in[6];
    const float* r      = (const float*)d_in[7];
    const float* weight = (const float*)d_in[8];
    float* out = (float*)d_out;

    const int N = in_sizes[0];

    precompute_kernel<<<(MDIM * GDIM + 127) / 128, 128>>>(mu_x, mu_y, mu_z,
                                                          sigmas, r, weight);

    dim3 grid((N + 255) / 256, MDIM);
    gauss_kernel<<<grid, 128>>>(x, y, z, out, N);
}

// round 2
// speedup vs baseline: 1.1269x; 1.1269x over previous
#include <cuda_runtime.h>
#include <cuda_bf16.h>

// M=64, G=48, N=4096, GRID_RANGE=2.0
// Inputs: 0:x(N) 1:y(N) 2:z(N) 3:mu_x(M*G) 4:mu_y(M*G) 5:mu_z(M*G)
//         6:sigmas(M*G*3) 7:r(M*G*4) 8:weight(M*G)
// Output: float (N, M) row-major.

#define MDIM 64
#define GDIM 48

typedef unsigned long long u64;

__device__ __forceinline__ u64 pack2(float lo, float hi) {
    u64 r; asm("mov.b64 %0, {%1, %2};" : "=l"(r) : "f"(lo), "f"(hi)); return r;
}
__device__ __forceinline__ void unpack2(u64 v, float& lo, float& hi) {
    asm("mov.b64 {%0, %1}, %2;" : "=f"(lo), "=f"(hi) : "l"(v));
}
__device__ __forceinline__ u64 ffma2(u64 a, u64 b, u64 c) {
    u64 r; asm("fma.rn.f32x2 %0, %1, %2, %3;" : "=l"(r) : "l"(a), "l"(b), "l"(c)); return r;
}
__device__ __forceinline__ u64 fmul2(u64 a, u64 b) {
    u64 r; asm("mul.rn.f32x2 %0, %1, %2;" : "=l"(r) : "l"(a), "l"(b)); return r;
}
__device__ __forceinline__ u64 fadd2(u64 a, u64 b) {
    u64 r; asm("add.rn.f32x2 %0, %1, %2;" : "=l"(r) : "l"(a), "l"(b)); return r;
}
__device__ __forceinline__ float fast_exp2(float q) {
    float p; asm("ex2.approx.ftz.f32 %0, %1;" : "=f"(p) : "f"(q)); return p;
}

// Fused kernel: one m per block (blockIdx.y). Block prologue computes the 48
// per-gaussian polynomial coefficient sets for this m and stores each coeff
// DUPLICATED ({v,v}) in smem so the main loop's LDS.128 reads yield ready-made
// f32x2 operands (no per-iteration packing).
//
// Coeff layout per g (24 floats = 6 x float4 = 6 x ulonglong2):
//   d2[0] = {a00,a00 | a11,a11}
//   d2[1] = {a22,a22 | 2a01,2a01}
//   d2[2] = {2a02,2a02 | 2a12,2a12}
//   d2[3] = {b0,b0 | b1,b1}
//   d2[4] = {b2,b2 | c,c}
//   d2[5] = {w,w | 0,0}
// where A = -0.5*log2(e) * R diag(1/s^2) R^T, b = -2 A mu, c = mu^T A mu,
// so pdf = exp2( x^T A x + b.x + c ).
__global__ __launch_bounds__(64) void gauss_fused_kernel(
    const float* __restrict__ xs, const float* __restrict__ ys,
    const float* __restrict__ zs,
    const float* __restrict__ mu_x, const float* __restrict__ mu_y,
    const float* __restrict__ mu_z, const float* __restrict__ sigmas,
    const float* __restrict__ rq, const float* __restrict__ weight,
    float* __restrict__ out, int N) {
    __shared__ __align__(16) float scoef[GDIM * 24];

    const int m = blockIdx.y;
    const int t = threadIdx.x;

    // ---- per-block coefficient precompute (threads 0..47) ----
    if (t < GDIM) {
        const int idx = m * GDIM + t;
        float qw = rq[idx * 4 + 0];
        float qx = rq[idx * 4 + 1];
        float qy = rq[idx * 4 + 2];
        float qz = rq[idx * 4 + 3];
        float inv = rsqrtf(qw * qw + qx * qx + qy * qy + qz * qz);
        qw *= inv; qx *= inv; qy *= inv; qz *= inv;

        float R[3][3];
        R[0][0] = 1.f - 2.f * (qy * qy + qz * qz);
        R[0][1] = 2.f * (qx * qy - qw * qz);
        R[0][2] = 2.f * (qx * qz + qw * qy);
        R[1][0] = 2.f * (qx * qy + qw * qz);
        R[1][1] = 1.f - 2.f * (qx * qx + qz * qz);
        R[1][2] = 2.f * (qy * qz - qw * qx);
        R[2][0] = 2.f * (qx * qz - qw * qy);
        R[2][1] = 2.f * (qy * qz + qw * qx);
        R[2][2] = 1.f - 2.f * (qx * qx + qy * qy);

        float s0 = sigmas[idx * 3 + 0];
        float s1 = sigmas[idx * 3 + 1];
        float s2 = sigmas[idx * 3 + 2];
        float is0 = 1.f / (s0 * s0);
        float is1 = 1.f / (s1 * s1);
        float is2 = 1.f / (s2 * s2);

        const float kk = -0.72134752044448169f;  // -0.5 * log2(e)
        float A[3][3];
        #pragma unroll
        for (int i = 0; i < 3; ++i)
            #pragma unroll
            for (int j = 0; j < 3; ++j)
                A[i][j] = kk * (R[i][0] * R[j][0] * is0 +
                                R[i][1] * R[j][1] * is1 +
                                R[i][2] * R[j][2] * is2);

        float m0 = mu_x[idx], m1 = mu_y[idx], m2 = mu_z[idx];
        float b0 = -2.f * (A[0][0] * m0 + A[0][1] * m1 + A[0][2] * m2);
        float b1 = -2.f * (A[1][0] * m0 + A[1][1] * m1 + A[1][2] * m2);
        float b2 = -2.f * (A[2][0] * m0 + A[2][1] * m1 + A[2][2] * m2);
        float c  = A[0][0] * m0 * m0 + A[1][1] * m1 * m1 + A[2][2] * m2 * m2
                 + 2.f * (A[0][1] * m0 * m1 + A[0][2] * m0 * m2 + A[1][2] * m1 * m2);
        float w = weight[idx];

        float* d = scoef + t * 24;
        d[0]  = A[0][0];       d[1]  = A[0][0];
        d[2]  = A[1][1];       d[3]  = A[1][1];
        d[4]  = A[2][2];       d[5]  = A[2][2];
        d[6]  = 2.f * A[0][1]; d[7]  = 2.f * A[0][1];
        d[8]  = 2.f * A[0][2]; d[9]  = 2.f * A[0][2];
        d[10] = 2.f * A[1][2]; d[11] = 2.f * A[1][2];
        d[12] = b0;            d[13] = b0;
        d[14] = b1;            d[15] = b1;
        d[16] = b2;            d[17] = b2;
        d[18] = c;             d[19] = c;
        d[20] = w;             d[21] = w;
        d[22] = 0.f;           d[23] = 0.f;
    }
    __syncthreads();

    // ---- main loop: 4 points per thread, packed as 2 f32x2 pairs ----
    const int nbase = blockIdx.x * 256 + t;   // points nbase + {0,64,128,192}

    float px[4], py[4], pz[4];
    #pragma unroll
    for (int p = 0; p < 4; ++p) {
        const int n = nbase + p * 64;
        if (n < N) {
            px[p] = xs[n];
            py[p] = ys[n] + 1.f;  // (y+1)/2 * GRID_RANGE, GRID_RANGE=2
            pz[p] = zs[n] + 1.f;
        } else {
            px[p] = py[p] = pz[p] = 0.f;
        }
    }

    u64 X[2], Y[2], Z[2], XX[2], YY[2], ZZ[2], XY[2], XZ[2], YZ[2], ACC[2];
    #pragma unroll
    for (int p = 0; p < 2; ++p) {
        X[p] = pack2(px[2 * p], px[2 * p + 1]);
        Y[p] = pack2(py[2 * p], py[2 * p + 1]);
        Z[p] = pack2(pz[2 * p], pz[2 * p + 1]);
        XX[p] = fmul2(X[p], X[p]);
        YY[p] = fmul2(Y[p], Y[p]);
        ZZ[p] = fmul2(Z[p], Z[p]);
        XY[p] = fmul2(X[p], Y[p]);
        XZ[p] = fmul2(X[p], Z[p]);
        YZ[p] = fmul2(Y[p], Z[p]);
        ACC[p] = pack2(0.f, 0.f);
    }

    const ulonglong2* __restrict__ sd = reinterpret_cast<const ulonglong2*>(scoef);

    #pragma unroll
    for (int g = 0; g < GDIM; ++g) {
        const ulonglong2 c0 = sd[g * 6 + 0];  // a00p | a11p
        const ulonglong2 c1 = sd[g * 6 + 1];  // a22p | 2a01p
        const ulonglong2 c2 = sd[g * 6 + 2];  // 2a02p | 2a12p
        const ulonglong2 c3 = sd[g * 6 + 3];  // b0p | b1p
        const ulonglong2 c4 = sd[g * 6 + 4];  // b2p | cp
        const ulonglong2 c5 = sd[g * 6 + 5];  // wp | 0

        #pragma unroll
        for (int p = 0; p < 2; ++p) {
            // two 5-deep chains instead of one 10-deep chain
            u64 qa = ffma2(c0.x, XX[p], c4.y);
            qa = ffma2(c0.y, YY[p], qa);
            qa = ffma2(c1.y, XY[p], qa);
            qa = ffma2(c3.x, X[p], qa);
            qa = ffma2(c3.y, Y[p], qa);
            u64 qb = fmul2(c1.x, ZZ[p]);
            qb = ffma2(c2.x, XZ[p], qb);
            qb = ffma2(c2.y, YZ[p], qb);
            qb = ffma2(c4.x, Z[p], qb);
            u64 q = fadd2(qa, qb);
            float qlo, qhi;
            unpack2(q, qlo, qhi);
            u64 pdf = pack2(fast_exp2(qlo), fast_exp2(qhi));
            ACC[p] = ffma2(c5.x, pdf, ACC[p]);
        }
    }

    #pragma unroll
    for (int p = 0; p < 2; ++p) {
        float a0, a1;
        unpack2(ACC[p], a0, a1);
        const int n0 = nbase + (2 * p) * 64;
        const int n1 = nbase + (2 * p + 1) * 64;
        if (n0 < N) out[n0 * MDIM + m] = a0;
        if (n1 < N) out[n1 * MDIM + m] = a1;
    }
}

extern "C" void kernel_launch(void* const* d_in, const int* in_sizes, int n_in,
                              void* d_out, int out_size) {
    const float* x      = (const float*)d_in[0];
    const float* y      = (const float*)d_in[1];
    const float* z      = (const float*)d_in[2];
    const float* mu_x   = (const float*)d_in[3];
    const float* mu_y   = (const float*)d_in[4];
    const float* mu_z   = (const float*)d_in[5];
    const float* sigmas = (const float*)d_in[6];
    const float* r      = (const float*)d_in[7];
    const float* weight = (const float*)d_in[8];
    float* out = (float*)d_out;

    const int N = in_sizes[0];

    dim3 grid((N + 255) / 256, MDIM);
    gauss_fused_kernel<<<grid, 64>>>(x, y, z, mu_x, mu_y, mu_z,
                                     sigmas, r, weight, out, N);
}

// round 3
// speedup vs baseline: 1.4795x; 1.3129x over previous
#include <cuda_runtime.h>
#include <cuda_bf16.h>

// M=64, G=48, N=4096, GRID_RANGE=2.0
// Inputs: 0:x(N) 1:y(N) 2:z(N) 3:mu_x(M*G) 4:mu_y(M*G) 5:mu_z(M*G)
//         6:sigmas(M*G*3) 7:r(M*G*4) 8:weight(M*G)
// Output: float (N, M) row-major.

#define MDIM 64
#define GDIM 48

__device__ __forceinline__ float fast_exp2(float q) {
    float p; asm("ex2.approx.ftz.f32 %0, %1;" : "=f"(p) : "f"(q)); return p;
}

// One m per block (blockIdx.y). Block prologue computes this m's 48 polynomial
// coefficient sets:
//   A = -0.5*log2(e) * R diag(1/s^2) R^T,  b = -2 A mu,  c = mu^T A mu
//   pdf = exp2( x^T A x + b.x + c ),  out = sum_g w * pdf
// Then a block-uniform predicate detects the isotropic case (A = a*I exactly,
// which holds for identity quaternions + equal sigmas) and runs a 5-FMA/eval
// specialized loop; otherwise the generic 10-FMA/eval loop runs.
__global__ __launch_bounds__(128) void gauss_fused_kernel(
    const float* __restrict__ xs, const float* __restrict__ ys,
    const float* __restrict__ zs,
    const float* __restrict__ mu_x, const float* __restrict__ mu_y,
    const float* __restrict__ mu_z, const float* __restrict__ sigmas,
    const float* __restrict__ rq, const float* __restrict__ weight,
    float* __restrict__ out, int N) {
    // generic layout: 3 x float4 per g
    __shared__ __align__(16) float4 sg[GDIM * 3];
    // isotropic fast layout: {a, b0, b1, b2} + {c, w}
    __shared__ __align__(16) float4 sA[GDIM];
    __shared__ __align__(8)  float2 sCW[GDIM];

    const int m = blockIdx.y;
    const int t = threadIdx.x;

    int iso_pred = 1;
    if (t < GDIM) {
        const int idx = m * GDIM + t;
        float qw = rq[idx * 4 + 0];
        float qx = rq[idx * 4 + 1];
        float qy = rq[idx * 4 + 2];
        float qz = rq[idx * 4 + 3];
        float inv = rsqrtf(qw * qw + qx * qx + qy * qy + qz * qz);
        qw *= inv; qx *= inv; qy *= inv; qz *= inv;

        float R[3][3];
        R[0][0] = 1.f - 2.f * (qy * qy + qz * qz);
        R[0][1] = 2.f * (qx * qy - qw * qz);
        R[0][2] = 2.f * (qx * qz + qw * qy);
        R[1][0] = 2.f * (qx * qy + qw * qz);
        R[1][1] = 1.f - 2.f * (qx * qx + qz * qz);
        R[1][2] = 2.f * (qy * qz - qw * qx);
        R[2][0] = 2.f * (qx * qz - qw * qy);
        R[2][1] = 2.f * (qy * qz + qw * qx);
        R[2][2] = 1.f - 2.f * (qx * qx + qy * qy);

        float s0 = sigmas[idx * 3 + 0];
        float s1 = sigmas[idx * 3 + 1];
        float s2 = sigmas[idx * 3 + 2];
        float is0 = 1.f / (s0 * s0);
        float is1 = 1.f / (s1 * s1);
        float is2 = 1.f / (s2 * s2);

        const float kk = -0.72134752044448169f;  // -0.5 * log2(e)
        float A[3][3];
        #pragma unroll
        for (int i = 0; i < 3; ++i)
            #pragma unroll
            for (int j = 0; j < 3; ++j)
                A[i][j] = kk * (R[i][0] * R[j][0] * is0 +
                                R[i][1] * R[j][1] * is1 +
                                R[i][2] * R[j][2] * is2);

        float m0 = mu_x[idx], m1 = mu_y[idx], m2 = mu_z[idx];
        float b0 = -2.f * (A[0][0] * m0 + A[0][1] * m1 + A[0][2] * m2);
        float b1 = -2.f * (A[1][0] * m0 + A[1][1] * m1 + A[1][2] * m2);
        float b2 = -2.f * (A[2][0] * m0 + A[2][1] * m1 + A[2][2] * m2);
        float c  = A[0][0] * m0 * m0 + A[1][1] * m1 * m1 + A[2][2] * m2 * m2
                 + 2.f * (A[0][1] * m0 * m1 + A[0][2] * m0 * m2 + A[1][2] * m1 * m2);
        float w = weight[idx];

        sg[t * 3 + 0] = make_float4(A[0][0], A[1][1], A[2][2], 2.f * A[0][1]);
        sg[t * 3 + 1] = make_float4(2.f * A[0][2], 2.f * A[1][2], b0, b1);
        sg[t * 3 + 2] = make_float4(b2, c, w, 0.f);

        sA[t]  = make_float4(A[0][0], b0, b1, b2);
        sCW[t] = make_float2(c, w);

        iso_pred = (A[0][1] == 0.f) & (A[0][2] == 0.f) & (A[1][2] == 0.f) &
                   (A[0][0] == A[1][1]) & (A[0][0] == A[2][2]);
    }
    const int iso = __syncthreads_and(iso_pred);

    // ---- main loop: 2 points per thread ----
    const int n0 = blockIdx.x * 256 + t;
    const int n1 = n0 + 128;

    float x0 = 0.f, y0 = 0.f, z0 = 0.f;
    float x1 = 0.f, y1 = 0.f, z1 = 0.f;
    if (n0 < N) { x0 = xs[n0]; y0 = ys[n0] + 1.f; z0 = zs[n0] + 1.f; }
    if (n1 < N) { x1 = xs[n1]; y1 = ys[n1] + 1.f; z1 = zs[n1] + 1.f; }

    float acc0 = 0.f, acc1 = 0.f;

    if (iso) {
        // A = a*I exactly: q = a*(x^2+y^2+z^2) + b.p + c
        float s20 = fmaf(z0, z0, fmaf(y0, y0, x0 * x0));
        float s21 = fmaf(z1, z1, fmaf(y1, y1, x1 * x1));
        #pragma unroll
        for (int g = 0; g < GDIM; ++g) {
            const float4 A4 = sA[g];
            const float2 cw = sCW[g];

            float q0 = fmaf(A4.x, s20, cw.x);
            q0 = fmaf(A4.y, x0, q0);
            q0 = fmaf(A4.z, y0, q0);
            q0 = fmaf(A4.w, z0, q0);

            float q1 = fmaf(A4.x, s21, cw.x);
            q1 = fmaf(A4.y, x1, q1);
            q1 = fmaf(A4.z, y1, q1);
            q1 = fmaf(A4.w, z1, q1);

            acc0 = fmaf(cw.y, fast_exp2(q0), acc0);
            acc1 = fmaf(cw.y, fast_exp2(q1), acc1);
        }
    } else {
        const float xx0 = x0 * x0, yy0 = y0 * y0, zz0 = z0 * z0;
        const float xy0 = x0 * y0, xz0 = x0 * z0, yz0 = y0 * z0;
        const float xx1 = x1 * x1, yy1 = y1 * y1, zz1 = z1 * z1;
        const float xy1 = x1 * y1, xz1 = x1 * z1, yz1 = y1 * z1;
        #pragma unroll
        for (int g = 0; g < GDIM; ++g) {
            const float4 cA = sg[g * 3 + 0];
            const float4 cB = sg[g * 3 + 1];
            const float4 cC = sg[g * 3 + 2];

            float q0 = cC.y;
            q0 = fmaf(cA.x, xx0, q0);
            q0 = fmaf(cA.y, yy0, q0);
            q0 = fmaf(cA.z, zz0, q0);
            q0 = fmaf(cA.w, xy0, q0);
            q0 = fmaf(cB.x, xz0, q0);
            q0 = fmaf(cB.y, yz0, q0);
            q0 = fmaf(cB.z, x0, q0);
            q0 = fmaf(cB.w, y0, q0);
            q0 = fmaf(cC.x, z0, q0);

            float q1 = cC.y;
            q1 = fmaf(cA.x, xx1, q1);
            q1 = fmaf(cA.y, yy1, q1);
            q1 = fmaf(cA.z, zz1, q1);
            q1 = fmaf(cA.w, xy1, q1);
            q1 = fmaf(cB.x, xz1, q1);
            q1 = fmaf(cB.y, yz1, q1);
            q1 = fmaf(cB.z, x1, q1);
            q1 = fmaf(cB.w, y1, q1);
            q1 = fmaf(cC.x, z1, q1);

            acc0 = fmaf(cC.z, fast_exp2(q0), acc0);
            acc1 = fmaf(cC.z, fast_exp2(q1), acc1);
        }
    }

    if (n0 < N) out[n0 * MDIM + m] = acc0;
    if (n1 < N) out[n1 * MDIM + m] = acc1;
}

extern "C" void kernel_launch(void* const* d_in, const int* in_sizes, int n_in,
                              void* d_out, int out_size) {
    const float* x      = (const float*)d_in[0];
    const float* y      = (const float*)d_in[1];
    const float* z      = (const float*)d_in[2];
    const float* mu_x   = (const float*)d_in[3];
    const float* mu_y   = (const float*)d_in[4];
    const float* mu_z   = (const float*)d_in[5];
    const float* sigmas = (const float*)d_in[6];
    const float* r      = (const float*)d_in[7];
    const float* weight = (const float*)d_in[8];
    float* out = (float*)d_out;

    const int N = in_sizes[0];

    dim3 grid((N + 255) / 256, MDIM);
    gauss_fused_kernel<<<grid, 128>>>(x, y, z, mu_x, mu_y, mu_z,
                                      sigmas, r, weight, out, N);
}